// round 5
// baseline (speedup 1.0000x reference)
#include <cuda_runtime.h>
#include <math.h>

#define SEQ  128
#define DIM  128
#define HIDN 341
#define HPAD 344     // padded cols for w1/w3 (÷4)
#define KPAD 352     // padded k for w2 (÷16)
#define VOC  8192
#define FEPS 1e-6f
#define NCTA 148
#define TCTA 64      // transformer CTAs (2 rows each)
#define NTHR 512
#define XS   132
#define AAS  352

// ---- persistent scratch ----
__device__ float g_k2[2][SEQ*DIM];
__device__ float g_v2[2][SEQ*DIM];
__device__ float g_xn[SEQ*DIM];
__device__ float g_bs[DIM*VOC];
__device__ float g_cs[DIM*VOC];
__device__ float g_sum[VOC];
__device__ float g_w1p[2][DIM*HPAD];
__device__ float g_w3p[2][DIM*HPAD];
__device__ float g_w2p[2][KPAD*DIM];
__device__ unsigned g_cnt_t = 0, g_gen_t = 0;
__device__ unsigned g_cnt_a = 0, g_gen_a = 0;
__device__ unsigned g_wcnt = 0;     // repack completion count (monotonic; data identical per replay)

__device__ __forceinline__ float sigf(float x) { return 1.f / (1.f + __expf(-x)); }

__device__ __forceinline__ float fset_le(float a, float b) {
    float r;
    asm("set.le.f32.f32 %0, %1, %2;" : "=f"(r) : "f"(a), "f"(b));
    return r;
}

__device__ __forceinline__ void gbar_n(unsigned n, unsigned* cnt, volatile unsigned* gen) {
    __threadfence();
    __syncthreads();
    if (threadIdx.x == 0) {
        unsigned my = *gen;
        __threadfence();
        unsigned a = atomicAdd(cnt, 1u);
        if (a == n - 1u) {
            *cnt = 0u;
            __threadfence();
            *gen = my + 1u;
        } else {
            while (*gen == my) __nanosleep(64);
        }
        __threadfence();
    }
    __syncthreads();
}

// sum of v*v over 128 lanes of row (t>>7), valid rows 0..1; all threads call
__device__ __forceinline__ float rowsum_sq(float v, float* red, int t) {
    int lane = t & 31, warp = t >> 5, r = t >> 7;
    float s = v * v;
    #pragma unroll
    for (int o = 16; o > 0; o >>= 1) s += __shfl_xor_sync(0xffffffffu, s, o);
    __syncthreads();
    if (lane == 0) red[warp] = s;
    __syncthreads();
    return red[r*4] + red[r*4+1] + red[r*4+2] + red[r*4+3];
}

// smem layout (floats)
#define OFF_KS   0        // 128*129 (K padded; aliased as mpart + precompute scratch)
#define OFF_VS   16512    // 128*128
#define OFF_XR   32896
#define OFF_QR   33152
#define OFF_HH   33408
#define OFF_CTX  33664
#define OFF_SC   33920    // 2*8*128
#define OFF_AA   35968    // 2*352
#define OFF_OUTS 36672    // 2*256
#define OFF_RED  37184    // 64
#define SMEM_FLOATS 38400
// logits aliases
#define LOFF_XT  0
#define LOFF_BS  16896
#define LOFF_CS  25088
#define LOFF_SUM 33280

extern "C" __global__ void __launch_bounds__(NTHR, 1)
topos_kernel(const int* __restrict__ idx, const float* __restrict__ w_raw,
             const float* __restrict__ norm1, const float* __restrict__ norm2,
             const float* __restrict__ wq, const float* __restrict__ wk,
             const float* __restrict__ wv, const float* __restrict__ wo,
             const float* __restrict__ w1, const float* __restrict__ w3,
             const float* __restrict__ w2, const float* __restrict__ fw,
             float* __restrict__ out)
{
    extern __shared__ float sm[];
    int c = blockIdx.x, t = threadIdx.x;
    int r0 = c * 2;

    float* ksv   = sm + OFF_KS;
    float* vsv   = sm + OFF_VS;
    float* xrv   = sm + OFF_XR;
    float* qrv   = sm + OFF_QR;
    float* hhv   = sm + OFF_HH;
    float* ctxv  = sm + OFF_CTX;
    float* scv   = sm + OFF_SC;
    float* aav   = sm + OFF_AA;
    float* outsv = sm + OFF_OUTS;
    float* redv  = sm + OFF_RED;
    float* mpart = sm + OFF_KS;     // GEMV partials (≤ 4128 floats)

    if (c < TCTA) {
        // ========================= transformer =========================
        if (t < 256) {
            int r = t >> 7, n = t & 127;
            xrv[r*128 + n] = sigf(w_raw[n*VOC + idx[r0 + r]]);
        }
        if (t < 8) { aav[HPAD + t] = 0.f; aav[AAS + HPAD + t] = 0.f; }  // (padding; cols 341..343 written as 0 later)
        __syncthreads();

        for (int l = 0; l < 2; l++) {
            const float* wq_l = wq + l*DIM*DIM;
            const float* wk_l = wk + l*DIM*DIM;
            const float* wv_l = wv + l*DIM*DIM;
            const float* wo_l = wo + l*DIM*DIM;
            const float* w1p_l = g_w1p[l];
            const float* w3p_l = g_w3p[l];
            const float* w2p_l = g_w2p[l];

            // ---- rmsnorm1 ----
            {
                int r = t >> 7, n = t & 127;
                float xv = (t < 256) ? xrv[r*128 + n] : 0.f;
                float rsum = rowsum_sq(xv, redv, t);
                if (t < 256)
                    hhv[r*128 + n] = xv * rsqrtf(rsum * (1.f/128.f) + FEPS) * norm1[l*DIM + n];
            }
            __syncthreads();

            // ---- qkv: 96 col-quads x 4 d-quarters ----
            if (t < 384) {
                int qd = t >> 2, dq = t & 3;
                int mat = qd >> 5, j = qd & 31;
                const float4* W4 = (const float4*)((mat == 0) ? wq_l : (mat == 1) ? wk_l : wv_l);
                int d0 = dq * 32;
                float a[8] = {0,0,0,0,0,0,0,0};
                #pragma unroll 1
                for (int db = 0; db < 32; db += 8) {
                    float4 w4[8];
                    #pragma unroll
                    for (int u = 0; u < 8; u++) w4[u] = W4[(d0+db+u)*32 + j];
                    #pragma unroll
                    for (int u = 0; u < 8; u++) {
                        float h0 = hhv[d0+db+u], h1 = hhv[128 + d0+db+u];
                        a[0]=fmaf(w4[u].x,h0,a[0]); a[1]=fmaf(w4[u].x,h1,a[1]);
                        a[2]=fmaf(w4[u].y,h0,a[2]); a[3]=fmaf(w4[u].y,h1,a[3]);
                        a[4]=fmaf(w4[u].z,h0,a[4]); a[5]=fmaf(w4[u].z,h1,a[5]);
                        a[6]=fmaf(w4[u].w,h0,a[6]); a[7]=fmaf(w4[u].w,h1,a[7]);
                    }
                }
                #pragma unroll
                for (int u = 0; u < 8; u++) mpart[t*8 + u] = a[u];
            }
            __syncthreads();
            for (int o = t; o < 768; o += NTHR) {      // reduce 4 d-quarters
                int sig = o >> 1, r = o & 1;
                int qd = sig >> 2, cc = sig & 3;
                int pi = qd*4*8 + cc*2 + r;
                float s = mpart[pi] + mpart[pi + 8] + mpart[pi + 16] + mpart[pi + 24];
                if (sig < 256) outsv[r*256 + sig] = s;                 // q,k
                else           g_v2[l][(r0+r)*128 + (sig & 127)] = s;  // v
            }
            __syncthreads();

            // ---- rope ----
            if (t < 256) {
                int rr = t >> 7, p = t & 127;
                int row = r0 + rr;
                int mat = p >> 6, pr = p & 63, hd = pr >> 3, j = pr & 7;
                int src = rr*256 + mat*128 + hd*16 + 2*j;
                float x0 = outsv[src], x1 = outsv[src+1];
                float invf = __expf(-1.1512925464970230f * (float)j);
                float f = (float)row * invf;
                float sn, cs0; sincosf(f, &sn, &cs0);
                float o0 = x0*cs0 - x1*sn;
                float o1 = x0*sn + x1*cs0;
                int dd = hd*16 + 2*j;
                if (mat == 0) { qrv[rr*128 + dd] = o0; qrv[rr*128 + dd + 1] = o1; }
                else          { g_k2[l][row*128 + dd] = o0; g_k2[l][row*128 + dd + 1] = o1; }
            }

            gbar_n(TCTA, &g_cnt_t, &g_gen_t);   // k,v published

            // ---- stage K (padded) + V ----
            {
                const float* gk = g_k2[l];
                const float* gv = g_v2[l];
                for (int i = t; i < 128*32; i += NTHR) {
                    int row = i >> 5, q4 = i & 31;
                    float4 kv = ((const float4*)(gk + row*128))[q4];
                    float* dk = ksv + row*129 + q4*4;
                    dk[0] = kv.x; dk[1] = kv.y; dk[2] = kv.z; dk[3] = kv.w;
                    ((float4*)(vsv + row*128))[q4] = ((const float4*)(gv + row*128))[q4];
                }
            }
            __syncthreads();

            // ---- scores + softmax: 16 warps = 2 rows x 8 heads ----
            {
                int lane = t & 31, warp = t >> 5;
                int r = warp >> 3, head = warp & 7;
                int i = r0 + r;
                float qreg[16];
                #pragma unroll
                for (int d = 0; d < 16; d++) qreg[d] = qrv[r*128 + head*16 + d];
                float sv[4];
                float m = -1e30f;
                #pragma unroll
                for (int jj = 0; jj < 4; jj++) {
                    int j = lane + 32*jj;
                    float s = -1e30f;
                    if (j <= i) {
                        const float* kp = ksv + j*129 + head*16;
                        float acc = 0.f;
                        #pragma unroll
                        for (int d = 0; d < 16; d++) acc = fmaf(qreg[d], kp[d], acc);
                        s = acc * 0.25f;
                    }
                    sv[jj] = s;
                    m = fmaxf(m, s);
                }
                #pragma unroll
                for (int o = 16; o > 0; o >>= 1) m = fmaxf(m, __shfl_xor_sync(0xffffffffu, m, o));
                float lsum = 0.f;
                #pragma unroll
                for (int jj = 0; jj < 4; jj++) {
                    int j = lane + 32*jj;
                    float e = (j <= i) ? __expf(sv[jj] - m) : 0.f;
                    sv[jj] = e; lsum += e;
                }
                #pragma unroll
                for (int o = 16; o > 0; o >>= 1) lsum += __shfl_xor_sync(0xffffffffu, lsum, o);
                float invs = 1.f / lsum;
                #pragma unroll
                for (int jj = 0; jj < 4; jj++)
                    scv[(r*8 + head)*128 + lane + 32*jj] = sv[jj] * invs;
            }
            __syncthreads();

            // ---- ctx = p @ v ----
            if (t < 256) {
                int r = t >> 7, n = t & 127, hd = (n >> 4);
                const float* pv = scv + (r*8 + hd)*128;
                float ac0=0.f, ac1=0.f, ac2=0.f, ac3=0.f;
                #pragma unroll 8
                for (int j = 0; j < 128; j += 4) {
                    ac0 = fmaf(pv[j],   vsv[j*128 + n],     ac0);
                    ac1 = fmaf(pv[j+1], vsv[(j+1)*128 + n], ac1);
                    ac2 = fmaf(pv[j+2], vsv[(j+2)*128 + n], ac2);
                    ac3 = fmaf(pv[j+3], vsv[(j+3)*128 + n], ac3);
                }
                ctxv[r*128 + n] = (ac0 + ac1) + (ac2 + ac3);
            }
            __syncthreads();

            // ---- o-proj: 32 quads x 16 d-segments ----
            {
                int qd = t >> 4, ds = t & 15;
                const float4* W4 = (const float4*)wo_l;
                float a[8] = {0,0,0,0,0,0,0,0};
                float4 w4[8];
                #pragma unroll
                for (int u = 0; u < 8; u++) w4[u] = W4[(ds*8+u)*32 + qd];
                #pragma unroll
                for (int u = 0; u < 8; u++) {
                    float c0 = ctxv[ds*8+u], c1 = ctxv[128 + ds*8+u];
                    a[0]=fmaf(w4[u].x,c0,a[0]); a[1]=fmaf(w4[u].x,c1,a[1]);
                    a[2]=fmaf(w4[u].y,c0,a[2]); a[3]=fmaf(w4[u].y,c1,a[3]);
                    a[4]=fmaf(w4[u].z,c0,a[4]); a[5]=fmaf(w4[u].z,c1,a[5]);
                    a[6]=fmaf(w4[u].w,c0,a[6]); a[7]=fmaf(w4[u].w,c1,a[7]);
                }
                #pragma unroll
                for (int u = 0; u < 8; u++) mpart[t*8 + u] = a[u];
            }
            __syncthreads();
            // ---- o reduce + residual + rmsnorm2 ----
            {
                int r = t >> 7, n = t & 127;
                float xnew = 0.f;
                if (t < 256) {
                    int qd = n >> 2, cc = n & 3;
                    float s = 0.f;
                    #pragma unroll
                    for (int ds = 0; ds < 16; ds++) s += mpart[(qd*16+ds)*8 + cc*2 + r];
                    xnew = xrv[r*128 + n] + s;
                    xrv[r*128 + n] = xnew;
                }
                float rsum = rowsum_sq(xnew, redv, t);
                if (t < 256)
                    hhv[r*128 + n] = xnew * rsqrtf(rsum * (1.f/128.f) + FEPS) * norm2[l*DIM + n];
            }
            __syncthreads();

            // wait once for repacked MLP weights
            if (l == 0) {
                if (t == 0) { while (atomicAdd(&g_wcnt, 0u) < 84u) __nanosleep(32); }
                __syncthreads();
            }

            // ---- MLP up: 86 quads x 2 mats x 3 d-segs ----
            for (int task = t; task < 516; task += NTHR) {
                int qd = task / 6, rem = task - qd*6;
                int mat = rem / 3, sg = rem - mat*3;
                const float4* W4 = (const float4*)((mat == 0) ? w1p_l : w3p_l);
                int d0 = sg * 48;
                int d1 = (sg == 2) ? 128 : d0 + 48;
                float a[8] = {0,0,0,0,0,0,0,0};
                #pragma unroll 1
                for (int db = d0; db < d1; db += 8) {
                    float4 w4[8];
                    #pragma unroll
                    for (int u = 0; u < 8; u++) w4[u] = W4[(db+u)*(HPAD/4) + qd];
                    #pragma unroll
                    for (int u = 0; u < 8; u++) {
                        float h0 = hhv[db+u], h1 = hhv[128 + db+u];
                        a[0]=fmaf(w4[u].x,h0,a[0]); a[1]=fmaf(w4[u].x,h1,a[1]);
                        a[2]=fmaf(w4[u].y,h0,a[2]); a[3]=fmaf(w4[u].y,h1,a[3]);
                        a[4]=fmaf(w4[u].z,h0,a[4]); a[5]=fmaf(w4[u].z,h1,a[5]);
                        a[6]=fmaf(w4[u].w,h0,a[6]); a[7]=fmaf(w4[u].w,h1,a[7]);
                    }
                }
                #pragma unroll
                for (int u = 0; u < 8; u++) mpart[task*8 + u] = a[u];
            }
            __syncthreads();
            for (int o = t; o < 688; o += NTHR) {     // reduce + silu
                int col = o >> 1, r = o & 1;
                int qd = col >> 2, cc = col & 3;
                int b1 = (qd*6)*8 + cc*2 + r;
                int b3 = (qd*6+3)*8 + cc*2 + r;
                float gg = mpart[b1] + mpart[b1+8] + mpart[b1+16];
                float uu = mpart[b3] + mpart[b3+8] + mpart[b3+16];
                aav[r*AAS + col] = gg * sigf(gg) * uu;   // cols 341..343 -> 0
            }
            __syncthreads();

            // ---- MLP down: 32 quads x 16 k-segments (22 each over KPAD=352) ----
            {
                int qd = t >> 4, ks = t & 15;
                const float4* W4 = (const float4*)w2p_l;
                int k0 = ks * 22;
                float a[8] = {0,0,0,0,0,0,0,0};
                #pragma unroll 1
                for (int kb = k0; kb < k0 + 22; kb += 11) {
                    float4 w4[11];
                    #pragma unroll
                    for (int u = 0; u < 11; u++) w4[u] = W4[(kb+u)*32 + qd];
                    #pragma unroll
                    for (int u = 0; u < 11; u++) {
                        float v0 = aav[kb+u], v1 = aav[AAS + kb+u];
                        a[0]=fmaf(w4[u].x,v0,a[0]); a[1]=fmaf(w4[u].x,v1,a[1]);
                        a[2]=fmaf(w4[u].y,v0,a[2]); a[3]=fmaf(w4[u].y,v1,a[3]);
                        a[4]=fmaf(w4[u].z,v0,a[4]); a[5]=fmaf(w4[u].z,v1,a[5]);
                        a[6]=fmaf(w4[u].w,v0,a[6]); a[7]=fmaf(w4[u].w,v1,a[7]);
                    }
                }
                #pragma unroll
                for (int u = 0; u < 8; u++) mpart[t*8 + u] = a[u];
            }
            __syncthreads();
            if (t < 256) {
                int r = t >> 7, n = t & 127;
                int qd = n >> 2, cc = n & 3;
                float s = 0.f;
                #pragma unroll
                for (int ks = 0; ks < 16; ks++) s += mpart[(qd*16+ks)*8 + cc*2 + r];
                xrv[r*128 + n] += s;
            }
            __syncthreads();
        } // layers

        // ---- final rmsnorm + L2 normalize ----
        {
            int r = t >> 7, n = t & 127;
            float xv = (t < 256) ? xrv[r*128 + n] : 0.f;
            float rsum = rowsum_sq(xv, redv, t);
            float v1 = xv * rsqrtf(rsum * (1.f/128.f) + FEPS) * ((t < 256) ? fw[n] : 0.f);
            float rsum2 = rowsum_sq(v1, redv, t);
            if (t < 256) g_xn[(r0 + r)*128 + n] = v1 * rsqrtf(rsum2);
        }
    } else {
        // ========================= idle CTAs: repack + logits tables =========================
        int i = c - TCTA;                       // 0..83
        unsigned g = (unsigned)i * NTHR + t;    // 0..43007
        // repack w1,w3 -> [128][344] padded
        for (unsigned e = g; e < 2u*128u*HPAD; e += 84u*NTHR) {
            unsigned l = e / (128u*HPAD), rem = e % (128u*HPAD);
            unsigned d = rem / HPAD, col = rem % HPAD;
            float v1 = 0.f, v3 = 0.f;
            if (col < HIDN) {
                v1 = w1[(l*128u + d)*HIDN + col];
                v3 = w3[(l*128u + d)*HIDN + col];
            }
            g_w1p[l][d*HPAD + col] = v1;
            g_w3p[l][d*HPAD + col] = v3;
        }
        // repack w2 -> [352][128] padded
        for (unsigned e = g; e < 2u*KPAD*128u; e += 84u*NTHR) {
            unsigned l = e / (KPAD*128u), rem = e % (KPAD*128u);
            unsigned k = rem / 128u, n = rem % 128u;
            g_w2p[l][k*128u + n] = (k < HIDN) ? w2[(l*HIDN + k)*128u + n] : 0.f;
        }
        __threadfence();
        __syncthreads();
        if (t == 0) atomicAdd(&g_wcnt, 1u);

        // sigmoid tables: 98 cols x 4 d-quarters
        {
            int j = t & 127, dq = t >> 7;
            int col = i*98 + j;
            bool valid = (j < 98) && (col < VOC);
            float s[32];
            float ssq = 0.f;
            if (valid) {
                #pragma unroll 1
                for (int u4 = 0; u4 < 32; u4 += 8) {
                    float w[8];
                    #pragma unroll
                    for (int u = 0; u < 8; u++) w[u] = w_raw[(dq*32 + u4+u)*VOC + col];
                    #pragma unroll
                    for (int u = 0; u < 8; u++) {
                        float b = sigf(w[u]);
                        s[u4+u] = b;
                        ssq = fmaf(b, b, ssq);
                    }
                }
            }
            sm[dq*128 + j] = ssq;
            __syncthreads();
            float scale = rsqrtf(sm[j] + sm[128+j] + sm[256+j] + sm[384+j]);
            float csum = 0.f;
            if (valid) {
                #pragma unroll 4
                for (int u = 0; u < 32; u++) {
                    float b = s[u] * scale;
                    csum += b;
                    g_bs[(dq*32+u)*VOC + col] = b;
                    g_cs[(dq*32+u)*VOC + col] = 1.f - b;
                }
            }
            sm[512 + dq*128 + j] = csum;
            __syncthreads();
            if (dq == 0 && valid)
                g_sum[col] = sm[512+j] + sm[640+j] + sm[768+j] + sm[896+j];
        }
    }

    gbar_n(NCTA, &g_cnt_a, &g_gen_a);   // x_n + tables published

    // ========================= logits main: CTA c<128, 64 vocab cols each =========================
    if (c < 128) {
        float* xT   = sm + LOFF_XT;
        float* bst  = sm + LOFF_BS;
        float* cst  = sm + LOFF_CS;
        float* sumv = sm + LOFF_SUM;
        int col0 = c * 64;

        for (int i = t; i < 128*16; i += NTHR) {
            int d = i >> 4, j4 = i & 15;
            ((float4*)(bst + d*64))[j4] = ((const float4*)(g_bs + d*VOC + col0))[j4];
            ((float4*)(cst + d*64))[j4] = ((const float4*)(g_cs + d*VOC + col0))[j4];
        }
        for (int i = t; i < SEQ*DIM; i += NTHR) {
            int s = i >> 7, d = i & 127;
            xT[d*XS + s] = g_xn[i];
        }
        if (t < 64) sumv[t] = g_sum[col0 + t];
        __syncthreads();

        int vp = t & 31, sq = t >> 5;
        const float invd = 1.f/128.f, lo = 1e-6f, hi = 1.f - 1e-6f;
        float acA[8] = {0,0,0,0,0,0,0,0};
        float acB[8] = {0,0,0,0,0,0,0,0};
        #pragma unroll 4
        for (int d = 0; d < 128; d++) {
            const float* xr = xT + d*XS + 8*sq;
            float4 xa = *(const float4*)(xr);
            float4 xb = *(const float4*)(xr + 4);
            float2 b2 = *(const float2*)(bst + d*64 + 2*vp);
            float2 c2 = *(const float2*)(cst + d*64 + 2*vp);
            acA[0] = fmaf(fset_le(xa.x, b2.x), c2.x, acA[0]);
            acB[0] = fmaf(fset_le(xa.x, b2.y), c2.y, acB[0]);
            acA[1] = fmaf(fset_le(xa.y, b2.x), c2.x, acA[1]);
            acB[1] = fmaf(fset_le(xa.y, b2.y), c2.y, acB[1]);
            acA[2] = fmaf(fset_le(xa.z, b2.x), c2.x, acA[2]);
            acB[2] = fmaf(fset_le(xa.z, b2.y), c2.y, acB[2]);
            acA[3] = fmaf(fset_le(xa.w, b2.x), c2.x, acA[3]);
            acB[3] = fmaf(fset_le(xa.w, b2.y), c2.y, acB[3]);
            acA[4] = fmaf(fset_le(xb.x, b2.x), c2.x, acA[4]);
            acB[4] = fmaf(fset_le(xb.x, b2.y), c2.y, acB[4]);
            acA[5] = fmaf(fset_le(xb.y, b2.x), c2.x, acA[5]);
            acB[5] = fmaf(fset_le(xb.y, b2.y), c2.y, acB[5]);
            acA[6] = fmaf(fset_le(xb.z, b2.x), c2.x, acA[6]);
            acB[6] = fmaf(fset_le(xb.z, b2.y), c2.y, acB[6]);
            acA[7] = fmaf(fset_le(xb.w, b2.x), c2.x, acA[7]);
            acB[7] = fmaf(fset_le(xb.w, b2.y), c2.y, acB[7]);
        }
        float sA = sumv[2*vp], sB = sumv[2*vp + 1];
        #pragma unroll
        for (int rr = 0; rr < 8; rr++) {
            float2 o;
            o.x = fminf(fmaxf((sA + acA[rr]) * invd, lo), hi);
            o.y = fminf(fmaxf((sB + acB[rr]) * invd, lo), hi);
            *(float2*)(out + (8*sq + rr)*VOC + col0 + 2*vp) = o;
        }
    }
}

// ---------------------------------------------------------------------------
extern "C" void kernel_launch(void* const* d_in, const int* in_sizes, int n_in,
                              void* d_out, int out_size) {
    const int*   idx   = (const int*)  d_in[0];
    const float* w_raw = (const float*)d_in[1];
    const float* norm1 = (const float*)d_in[2];
    const float* norm2 = (const float*)d_in[3];
    const float* wq    = (const float*)d_in[4];
    const float* wk    = (const float*)d_in[5];
    const float* wv    = (const float*)d_in[6];
    const float* wo    = (const float*)d_in[7];
    const float* w1    = (const float*)d_in[8];
    const float* w3    = (const float*)d_in[9];
    const float* w2    = (const float*)d_in[10];
    const float* fw    = (const float*)d_in[11];
    float* out = (float*)d_out;

    const int smem_bytes = SMEM_FLOATS * 4;
    cudaFuncSetAttribute(topos_kernel, cudaFuncAttributeMaxDynamicSharedMemorySize, smem_bytes);

    topos_kernel<<<NCTA, NTHR, smem_bytes>>>(idx, w_raw, norm1, norm2,
                                             wq, wk, wv, wo, w1, w3, w2, fw, out);
}

// round 6
// speedup vs baseline: 1.1949x; 1.1949x over previous
#include <cuda_runtime.h>
#include <math.h>

#define SEQ  128
#define DIM  128
#define HIDN 341
#define HPAD 344     // padded cols for w1/w3 (÷4)
#define KPAD 352     // padded k for w2
#define VOC  8192
#define FEPS 1e-6f
#define NCTA 148
#define TCTA 64
#define NTHR 512
#define XS   132
#define AAS  352

// ---- persistent scratch (16B aligned for float4 access) ----
__device__ __align__(16) float g_k2[2][SEQ*DIM];
__device__ __align__(16) float g_v2[2][SEQ*DIM];
__device__ __align__(16) float g_xn[SEQ*DIM];
__device__ __align__(16) float g_bs[DIM*VOC];
__device__ __align__(16) float g_cs[DIM*VOC];
__device__ __align__(16) float g_sum[VOC];
__device__ __align__(16) float g_w1p[2][DIM*HPAD + 8];   // +8: OOB-read pad for lane tails
__device__ __align__(16) float g_w3p[2][DIM*HPAD + 8];
__device__ __align__(16) float g_w2p[2][KPAD*DIM];
__device__ unsigned g_cnt_t = 0, g_gen_t = 0;
__device__ unsigned g_cnt_a = 0, g_gen_a = 0;
__device__ unsigned g_wcnt = 0;   // repack done-count (monotonic; repacked data identical each replay)

__device__ __forceinline__ float sigf(float x) { return 1.f / (1.f + __expf(-x)); }

__device__ __forceinline__ float fset_le(float a, float b) {
    float r;
    asm("set.le.f32.f32 %0, %1, %2;" : "=f"(r) : "f"(a), "f"(b));
    return r;
}

__device__ __forceinline__ void gbar_n(unsigned n, unsigned* cnt, volatile unsigned* gen) {
    __threadfence();
    __syncthreads();
    if (threadIdx.x == 0) {
        unsigned my = *gen;
        __threadfence();
        unsigned a = atomicAdd(cnt, 1u);
        if (a == n - 1u) {
            *cnt = 0u;
            __threadfence();
            *gen = my + 1u;
        } else {
            while (*gen == my) __nanosleep(64);
        }
        __threadfence();
    }
    __syncthreads();
}

// sum of v*v over 128 lanes of row (t>>7); all threads call
__device__ __forceinline__ float rowsum_sq(float v, float* red, int t) {
    int lane = t & 31, warp = t >> 5, r = t >> 7;
    float s = v * v;
    #pragma unroll
    for (int o = 16; o > 0; o >>= 1) s += __shfl_xor_sync(0xffffffffu, s, o);
    __syncthreads();
    if (lane == 0) red[warp] = s;
    __syncthreads();
    return red[r*4] + red[r*4+1] + red[r*4+2] + red[r*4+3];
}

// smem layout (floats)
#define OFF_KS   0        // 128*129 padded K; aliased by MLP-up raw sums
#define OFF_VS   16512    // 128*128
#define OFF_XR   32896
#define OFF_QR   33152
#define OFF_HH   33408
#define OFF_CTX  33664
#define OFF_SC   33920    // 2*8*128
#define OFF_AA   35968    // 2*352
#define OFF_OUTS 36672    // 2*256
#define OFF_RED  37184    // 64
#define SMEM_FLOATS 38400
// logits aliases
#define LOFF_XT  0
#define LOFF_BS  16896
#define LOFF_CS  25088
#define LOFF_SUM 33280

extern "C" __global__ void __launch_bounds__(NTHR, 1)
topos_kernel(const int* __restrict__ idx, const float* __restrict__ w_raw,
             const float* __restrict__ norm1, const float* __restrict__ norm2,
             const float* __restrict__ wq, const float* __restrict__ wk,
             const float* __restrict__ wv, const float* __restrict__ wo,
             const float* __restrict__ w1, const float* __restrict__ w3,
             const float* __restrict__ w2, const float* __restrict__ fw,
             float* __restrict__ out)
{
    extern __shared__ float sm[];
    int c = blockIdx.x, t = threadIdx.x;
    int r0 = c * 2;

    float* ksv   = sm + OFF_KS;
    float* vsv   = sm + OFF_VS;
    float* xrv   = sm + OFF_XR;
    float* qrv   = sm + OFF_QR;
    float* hhv   = sm + OFF_HH;
    float* ctxv  = sm + OFF_CTX;
    float* scv   = sm + OFF_SC;
    float* aav   = sm + OFF_AA;
    float* outsv = sm + OFF_OUTS;
    float* redv  = sm + OFF_RED;
    float* mup   = sm + OFF_KS;     // MLP-up raw sums (4*AAS = 1408 floats)

    if (c < TCTA) {
        // ========================= transformer: rows r0, r0+1 =========================
        if (t < 256) {
            int r = t >> 7, n = t & 127;
            xrv[r*128 + n] = sigf(w_raw[n*VOC + idx[r0 + r]]);
        }
        if (t < 8) { aav[HPAD + t] = 0.f; aav[AAS + HPAD + t] = 0.f; }  // zero 344..351 both rows
        __syncthreads();

        for (int l = 0; l < 2; l++) {
            const float* wq_l = wq + l*DIM*DIM;
            const float* wk_l = wk + l*DIM*DIM;
            const float* wv_l = wv + l*DIM*DIM;
            const float* wo_l = wo + l*DIM*DIM;
            const float* w1p_l = g_w1p[l];
            const float* w3p_l = g_w3p[l];
            const float* w2p_l = g_w2p[l];

            // ---- rmsnorm1 ----
            {
                int r = t >> 7, n = t & 127;
                float xv = (t < 256) ? xrv[r*128 + n] : 0.f;
                float rsum = rowsum_sq(xv, redv, t);
                if (t < 256)
                    hhv[r*128 + n] = xv * rsqrtf(rsum * (1.f/128.f) + FEPS) * norm1[l*DIM + n];
            }
            __syncthreads();

            // ---- qkv: 96 col-quads x 4 d-quarters; shfl-reduce over dq ----
            if (t < 384) {
                int qd = t >> 2, dq = t & 3;
                int mat = qd >> 5, j = qd & 31;
                const float4* W4 = (const float4*)((mat == 0) ? wq_l : (mat == 1) ? wk_l : wv_l);
                int d0 = dq * 32;
                float a[8] = {0,0,0,0,0,0,0,0};
                #pragma unroll 1
                for (int db = 0; db < 32; db += 8) {
                    float4 w4[8];
                    #pragma unroll
                    for (int u = 0; u < 8; u++) w4[u] = W4[(d0+db+u)*32 + j];
                    #pragma unroll
                    for (int u = 0; u < 8; u++) {
                        float h0 = hhv[d0+db+u], h1 = hhv[128 + d0+db+u];
                        a[0]=fmaf(w4[u].x,h0,a[0]); a[1]=fmaf(w4[u].x,h1,a[1]);
                        a[2]=fmaf(w4[u].y,h0,a[2]); a[3]=fmaf(w4[u].y,h1,a[3]);
                        a[4]=fmaf(w4[u].z,h0,a[4]); a[5]=fmaf(w4[u].z,h1,a[5]);
                        a[6]=fmaf(w4[u].w,h0,a[6]); a[7]=fmaf(w4[u].w,h1,a[7]);
                    }
                }
                #pragma unroll
                for (int u = 0; u < 8; u++) {
                    a[u] += __shfl_xor_sync(0xffffffffu, a[u], 1);
                    a[u] += __shfl_xor_sync(0xffffffffu, a[u], 2);
                }
                if (dq == 0) {
                    int colb = j*4;
                    if (mat < 2) {
                        #pragma unroll
                        for (int u = 0; u < 4; u++) {
                            outsv[0*256 + mat*128 + colb+u] = a[2*u];
                            outsv[1*256 + mat*128 + colb+u] = a[2*u+1];
                        }
                    } else {
                        #pragma unroll
                        for (int u = 0; u < 4; u++) {
                            g_v2[l][(r0+0)*128 + colb+u] = a[2*u];
                            g_v2[l][(r0+1)*128 + colb+u] = a[2*u+1];
                        }
                    }
                }
            }
            __syncthreads();

            // ---- rope: q -> smem, k -> global ----
            if (t < 256) {
                int rr = t >> 7, p = t & 127;
                int row = r0 + rr;
                int mat = p >> 6, pr = p & 63, hd = pr >> 3, j = pr & 7;
                int src = rr*256 + mat*128 + hd*16 + 2*j;
                float x0 = outsv[src], x1 = outsv[src+1];
                float invf = __expf(-1.1512925464970230f * (float)j);
                float f = (float)row * invf;
                float sn, cs0; sincosf(f, &sn, &cs0);
                float o0 = x0*cs0 - x1*sn;
                float o1 = x0*sn + x1*cs0;
                int dd = hd*16 + 2*j;
                if (mat == 0) { qrv[rr*128 + dd] = o0; qrv[rr*128 + dd + 1] = o1; }
                else          { g_k2[l][row*128 + dd] = o0; g_k2[l][row*128 + dd + 1] = o1; }
            }

            gbar_n(TCTA, &g_cnt_t, &g_gen_t);   // k,v published

            // ---- stage K (padded) + V ----
            {
                const float* gk = g_k2[l];
                const float* gv = g_v2[l];
                for (int i = t; i < 128*32; i += NTHR) {
                    int row = i >> 5, q4 = i & 31;
                    float4 kv = ((const float4*)(gk + row*128))[q4];
                    float* dk = ksv + row*129 + q4*4;
                    dk[0] = kv.x; dk[1] = kv.y; dk[2] = kv.z; dk[3] = kv.w;
                    ((float4*)(vsv + row*128))[q4] = ((const float4*)(gv + row*128))[q4];
                }
            }
            __syncthreads();

            // ---- scores + softmax: 16 warps = 2 rows x 8 heads ----
            {
                int lane = t & 31, warp = t >> 5;
                int r = warp >> 3, head = warp & 7;
                int i = r0 + r;
                float qreg[16];
                #pragma unroll
                for (int d = 0; d < 16; d++) qreg[d] = qrv[r*128 + head*16 + d];
                float sv[4];
                float m = -1e30f;
                #pragma unroll
                for (int jj = 0; jj < 4; jj++) {
                    int j = lane + 32*jj;
                    float s = -1e30f;
                    if (j <= i) {
                        const float* kp = ksv + j*129 + head*16;
                        float acc = 0.f;
                        #pragma unroll
                        for (int d = 0; d < 16; d++) acc = fmaf(qreg[d], kp[d], acc);
                        s = acc * 0.25f;
                    }
                    sv[jj] = s;
                    m = fmaxf(m, s);
                }
                #pragma unroll
                for (int o = 16; o > 0; o >>= 1) m = fmaxf(m, __shfl_xor_sync(0xffffffffu, m, o));
                float lsum = 0.f;
                #pragma unroll
                for (int jj = 0; jj < 4; jj++) {
                    int j = lane + 32*jj;
                    float e = (j <= i) ? __expf(sv[jj] - m) : 0.f;
                    sv[jj] = e; lsum += e;
                }
                #pragma unroll
                for (int o = 16; o > 0; o >>= 1) lsum += __shfl_xor_sync(0xffffffffu, lsum, o);
                float invs = 1.f / lsum;
                #pragma unroll
                for (int jj = 0; jj < 4; jj++)
                    scv[(r*8 + head)*128 + lane + 32*jj] = sv[jj] * invs;
            }
            __syncthreads();

            // ---- ctx = p @ v ----
            if (t < 256) {
                int r = t >> 7, n = t & 127, hd = (n >> 4);
                const float* pv = scv + (r*8 + hd)*128;
                float ac0=0.f, ac1=0.f, ac2=0.f, ac3=0.f;
                #pragma unroll 8
                for (int j = 0; j < 128; j += 4) {
                    ac0 = fmaf(pv[j],   vsv[j*128 + n],     ac0);
                    ac1 = fmaf(pv[j+1], vsv[(j+1)*128 + n], ac1);
                    ac2 = fmaf(pv[j+2], vsv[(j+2)*128 + n], ac2);
                    ac3 = fmaf(pv[j+3], vsv[(j+3)*128 + n], ac3);
                }
                ctxv[r*128 + n] = (ac0 + ac1) + (ac2 + ac3);
            }
            __syncthreads();

            // ---- o-proj: 32 quads x 4 d-quarters; shfl-reduce ----
            if (t < 128) {
                int qd = t >> 2, dq = t & 3;
                const float4* W4 = (const float4*)wo_l;
                int d0 = dq * 32;
                float a[8] = {0,0,0,0,0,0,0,0};
                #pragma unroll 1
                for (int db = 0; db < 32; db += 8) {
                    float4 w4[8];
                    #pragma unroll
                    for (int u = 0; u < 8; u++) w4[u] = W4[(d0+db+u)*32 + qd];
                    #pragma unroll
                    for (int u = 0; u < 8; u++) {
                        float c0 = ctxv[d0+db+u], c1 = ctxv[128 + d0+db+u];
                        a[0]=fmaf(w4[u].x,c0,a[0]); a[1]=fmaf(w4[u].x,c1,a[1]);
                        a[2]=fmaf(w4[u].y,c0,a[2]); a[3]=fmaf(w4[u].y,c1,a[3]);
                        a[4]=fmaf(w4[u].z,c0,a[4]); a[5]=fmaf(w4[u].z,c1,a[5]);
                        a[6]=fmaf(w4[u].w,c0,a[6]); a[7]=fmaf(w4[u].w,c1,a[7]);
                    }
                }
                #pragma unroll
                for (int u = 0; u < 8; u++) {
                    a[u] += __shfl_xor_sync(0xffffffffu, a[u], 1);
                    a[u] += __shfl_xor_sync(0xffffffffu, a[u], 2);
                }
                if (dq == 0) {
                    int colb = qd*4;
                    #pragma unroll
                    for (int u = 0; u < 4; u++) {
                        outsv[0*256 + colb+u] = a[2*u];
                        outsv[1*256 + colb+u] = a[2*u+1];
                    }
                }
            }
            __syncthreads();

            // ---- residual + rmsnorm2 ----
            {
                int r = t >> 7, n = t & 127;
                float xnew = 0.f;
                if (t < 256) {
                    xnew = xrv[r*128 + n] + outsv[r*256 + n];
                    xrv[r*128 + n] = xnew;
                }
                float rsum = rowsum_sq(xnew, redv, t);
                if (t < 256)
                    hhv[r*128 + n] = xnew * rsqrtf(rsum * (1.f/128.f) + FEPS) * norm2[l*DIM + n];
            }
            __syncthreads();

            // one-shot wait for repacked MLP weights (repack finishes far earlier)
            if (l == 0) {
                if (t == 0) { while (*(volatile unsigned*)&g_wcnt < 84u) __nanosleep(32); }
                __syncthreads();
            }

            // ---- MLP up: 86(+2 pad) quads x 2 mats x 2 d-halves; shfl-reduce over dh ----
            if (t < 352) {
                int sig = t >> 1, dh = t & 1;
                int qd = sig >> 1, mat = sig & 1;        // qd 0..87 (86,87 = discard lanes)
                const float4* W4 = (const float4*)((mat == 0) ? w1p_l : w3p_l);
                int d0 = dh * 64;
                float a[8] = {0,0,0,0,0,0,0,0};
                #pragma unroll 1
                for (int db = 0; db < 64; db += 8) {
                    float4 w4[8];
                    #pragma unroll
                    for (int u = 0; u < 8; u++) w4[u] = W4[(d0+db+u)*86 + qd];
                    #pragma unroll
                    for (int u = 0; u < 8; u++) {
                        float h0 = hhv[d0+db+u], h1 = hhv[128 + d0+db+u];
                        a[0]=fmaf(w4[u].x,h0,a[0]); a[1]=fmaf(w4[u].x,h1,a[1]);
                        a[2]=fmaf(w4[u].y,h0,a[2]); a[3]=fmaf(w4[u].y,h1,a[3]);
                        a[4]=fmaf(w4[u].z,h0,a[4]); a[5]=fmaf(w4[u].z,h1,a[5]);
                        a[6]=fmaf(w4[u].w,h0,a[6]); a[7]=fmaf(w4[u].w,h1,a[7]);
                    }
                }
                #pragma unroll
                for (int u = 0; u < 8; u++)
                    a[u] += __shfl_xor_sync(0xffffffffu, a[u], 1);
                if (dh == 0 && qd < 86) {
                    int colb = qd*4;
                    #pragma unroll
                    for (int u = 0; u < 4; u++) {
                        mup[(mat*2+0)*AAS + colb+u] = a[2*u];
                        mup[(mat*2+1)*AAS + colb+u] = a[2*u+1];
                    }
                }
            }
            __syncthreads();
            for (int o = t; o < 688; o += NTHR) {      // silu(g)*u ; padded cols give 0
                int r = (o >= 344) ? 1 : 0;
                int col = o - r*344;
                float gg = mup[(0+r)*AAS + col];
                float uu = mup[(2+r)*AAS + col];
                aav[r*AAS + col] = gg * sigf(gg) * uu;
            }
            __syncthreads();

            // ---- MLP down: 32 quads x 4 k-segments(88); shfl-reduce ----
            if (t < 128) {
                int qd = t >> 2, dq = t & 3;
                const float4* W4 = (const float4*)w2p_l;
                int k0 = dq * 88;
                float a[8] = {0,0,0,0,0,0,0,0};
                #pragma unroll 1
                for (int kb = 0; kb < 88; kb += 8) {
                    float4 w4[8];
                    #pragma unroll
                    for (int u = 0; u < 8; u++) w4[u] = W4[(k0+kb+u)*32 + qd];
                    #pragma unroll
                    for (int u = 0; u < 8; u++) {
                        float v0 = aav[k0+kb+u], v1 = aav[AAS + k0+kb+u];
                        a[0]=fmaf(w4[u].x,v0,a[0]); a[1]=fmaf(w4[u].x,v1,a[1]);
                        a[2]=fmaf(w4[u].y,v0,a[2]); a[3]=fmaf(w4[u].y,v1,a[3]);
                        a[4]=fmaf(w4[u].z,v0,a[4]); a[5]=fmaf(w4[u].z,v1,a[5]);
                        a[6]=fmaf(w4[u].w,v0,a[6]); a[7]=fmaf(w4[u].w,v1,a[7]);
                    }
                }
                #pragma unroll
                for (int u = 0; u < 8; u++) {
                    a[u] += __shfl_xor_sync(0xffffffffu, a[u], 1);
                    a[u] += __shfl_xor_sync(0xffffffffu, a[u], 2);
                }
                if (dq == 0) {
                    int colb = qd*4;
                    #pragma unroll
                    for (int u = 0; u < 4; u++) {
                        outsv[0*256 + colb+u] = a[2*u];
                        outsv[1*256 + colb+u] = a[2*u+1];
                    }
                }
            }
            __syncthreads();
            if (t < 256) {
                int r = t >> 7, n = t & 127;
                xrv[r*128 + n] += outsv[r*256 + n];
            }
            __syncthreads();
        } // layers

        // ---- final rmsnorm + L2 normalize ----
        {
            int r = t >> 7, n = t & 127;
            float xv = (t < 256) ? xrv[r*128 + n] : 0.f;
            float rsum = rowsum_sq(xv, redv, t);
            float v1 = xv * rsqrtf(rsum * (1.f/128.f) + FEPS) * ((t < 256) ? fw[n] : 0.f);
            float rsum2 = rowsum_sq(v1, redv, t);
            if (t < 256) g_xn[(r0 + r)*128 + n] = v1 * rsqrtf(rsum2);
        }
    } else {
        // ========================= idle CTAs: repack then logits tables =========================
        int i = c - TCTA;                       // 0..83
        unsigned g = (unsigned)i * NTHR + t;
        for (unsigned e = g; e < 2u*128u*HPAD; e += 84u*NTHR) {
            unsigned l = e / (128u*HPAD), rem = e % (128u*HPAD);
            unsigned d = rem / HPAD, col = rem % HPAD;
            float v1 = 0.f, v3 = 0.f;
            if (col < HIDN) {
                v1 = w1[(l*128u + d)*HIDN + col];
                v3 = w3[(l*128u + d)*HIDN + col];
            }
            g_w1p[l][d*HPAD + col] = v1;
            g_w3p[l][d*HPAD + col] = v3;
        }
        for (unsigned e = g; e < 2u*KPAD*128u; e += 84u*NTHR) {
            unsigned l = e / (KPAD*128u), rem = e % (KPAD*128u);
            unsigned k = rem / 128u, n = rem % 128u;
            g_w2p[l][k*128u + n] = (k < HIDN) ? w2[(l*HIDN + k)*128u + n] : 0.f;
        }
        __threadfence();
        __syncthreads();
        if (t == 0) atomicAdd(&g_wcnt, 1u);

        // sigmoid tables: 98 cols x 4 d-quarters per CTA
        {
            int j = t & 127, dq = t >> 7;
            int col = i*98 + j;
            bool valid = (j < 98) && (col < VOC);
            float s[32];
            float ssq = 0.f;
            if (valid) {
                #pragma unroll 1
                for (int u4 = 0; u4 < 32; u4 += 8) {
                    float w[8];
                    #pragma unroll
                    for (int u = 0; u < 8; u++) w[u] = w_raw[(dq*32 + u4+u)*VOC + col];
                    #pragma unroll
                    for (int u = 0; u < 8; u++) {
                        float b = sigf(w[u]);
                        s[u4+u] = b;
                        ssq = fmaf(b, b, ssq);
                    }
                }
            }
            sm[dq*128 + j] = ssq;
            __syncthreads();
            float scale = rsqrtf(sm[j] + sm[128+j] + sm[256+j] + sm[384+j]);
            float csum = 0.f;
            if (valid) {
                #pragma unroll 4
                for (int u = 0; u < 32; u++) {
                    float b = s[u] * scale;
                    csum += b;
                    g_bs[(dq*32+u)*VOC + col] = b;
                    g_cs[(dq*32+u)*VOC + col] = 1.f - b;
                }
            }
            sm[512 + dq*128 + j] = csum;
            __syncthreads();
            if (dq == 0 && valid)
                g_sum[col] = sm[512+j] + sm[640+j] + sm[768+j] + sm[896+j];
        }
    }

    gbar_n(NCTA, &g_cnt_a, &g_gen_a);   // x_n + tables published

    // ========================= logits main: CTA c<128, 64 vocab cols =========================
    if (c < 128) {
        float* xT   = sm + LOFF_XT;
        float* bst  = sm + LOFF_BS;
        float* cst  = sm + LOFF_CS;
        float* sumv = sm + LOFF_SUM;
        int col0 = c * 64;

        for (int i = t; i < 128*16; i += NTHR) {
            int d = i >> 4, j4 = i & 15;
            ((float4*)(bst + d*64))[j4] = ((const float4*)(g_bs + d*VOC + col0))[j4];
            ((float4*)(cst + d*64))[j4] = ((const float4*)(g_cs + d*VOC + col0))[j4];
        }
        for (int i = t; i < SEQ*DIM; i += NTHR) {
            int s = i >> 7, d = i & 127;
            xT[d*XS + s] = g_xn[i];
        }
        if (t < 64) sumv[t] = g_sum[col0 + t];
        __syncthreads();

        int vp = t & 31, sq = t >> 5;
        const float invd = 1.f/128.f, lo = 1e-6f, hi = 1.f - 1e-6f;
        float acA[8] = {0,0,0,0,0,0,0,0};
        float acB[8] = {0,0,0,0,0,0,0,0};
        #pragma unroll 4
        for (int d = 0; d < 128; d++) {
            const float* xr = xT + d*XS + 8*sq;
            float4 xa = *(const float4*)(xr);
            float4 xb = *(const float4*)(xr + 4);
            float2 b2 = *(const float2*)(bst + d*64 + 2*vp);
            float2 c2 = *(const float2*)(cst + d*64 + 2*vp);
            acA[0] = fmaf(fset_le(xa.x, b2.x), c2.x, acA[0]);
            acB[0] = fmaf(fset_le(xa.x, b2.y), c2.y, acB[0]);
            acA[1] = fmaf(fset_le(xa.y, b2.x), c2.x, acA[1]);
            acB[1] = fmaf(fset_le(xa.y, b2.y), c2.y, acB[1]);
            acA[2] = fmaf(fset_le(xa.z, b2.x), c2.x, acA[2]);
            acB[2] = fmaf(fset_le(xa.z, b2.y), c2.y, acB[2]);
            acA[3] = fmaf(fset_le(xa.w, b2.x), c2.x, acA[3]);
            acB[3] = fmaf(fset_le(xa.w, b2.y), c2.y, acB[3]);
            acA[4] = fmaf(fset_le(xb.x, b2.x), c2.x, acA[4]);
            acB[4] = fmaf(fset_le(xb.x, b2.y), c2.y, acB[4]);
            acA[5] = fmaf(fset_le(xb.y, b2.x), c2.x, acA[5]);
            acB[5] = fmaf(fset_le(xb.y, b2.y), c2.y, acB[5]);
            acA[6] = fmaf(fset_le(xb.z, b2.x), c2.x, acA[6]);
            acB[6] = fmaf(fset_le(xb.z, b2.y), c2.y, acB[6]);
            acA[7] = fmaf(fset_le(xb.w, b2.x), c2.x, acA[7]);
            acB[7] = fmaf(fset_le(xb.w, b2.y), c2.y, acB[7]);
        }
        float sA = sumv[2*vp], sB = sumv[2*vp + 1];
        #pragma unroll
        for (int rr = 0; rr < 8; rr++) {
            float2 o;
            o.x = fminf(fmaxf((sA + acA[rr]) * invd, lo), hi);
            o.y = fminf(fmaxf((sB + acB[rr]) * invd, lo), hi);
            *(float2*)(out + (8*sq + rr)*VOC + col0 + 2*vp) = o;
        }
    }
}

// ---------------------------------------------------------------------------
extern "C" void kernel_launch(void* const* d_in, const int* in_sizes, int n_in,
                              void* d_out, int out_size) {
    const int*   idx   = (const int*)  d_in[0];
    const float* w_raw = (const float*)d_in[1];
    const float* norm1 = (const float*)d_in[2];
    const float* norm2 = (const float*)d_in[3];
    const float* wq    = (const float*)d_in[4];
    const float* wk    = (const float*)d_in[5];
    const float* wv    = (const float*)d_in[6];
    const float* wo    = (const float*)d_in[7];
    const float* w1    = (const float*)d_in[8];
    const float* w3    = (const float*)d_in[9];
    const float* w2    = (const float*)d_in[10];
    const float* fw    = (const float*)d_in[11];
    float* out = (float*)d_out;

    const int smem_bytes = SMEM_FLOATS * 4;
    cudaFuncSetAttribute(topos_kernel, cudaFuncAttributeMaxDynamicSharedMemorySize, smem_bytes);

    topos_kernel<<<NCTA, NTHR, smem_bytes>>>(idx, w_raw, norm1, norm2,
                                             wq, wk, wv, wo, w1, w3, w2, fw, out);
}